// round 3
// baseline (speedup 1.0000x reference)
#include <cuda_runtime.h>
#include <math.h>

// ---------------- problem constants ----------------
static constexpr int B_   = 256;
static constexpr int D_   = 1024;
static constexpr int H_   = 8;
static constexpr int HD_  = 128;
static constexpr int P_   = 2048;
static constexpr int HID_ = 1024;   // H*HD
static constexpr int O_   = 1024;
static constexpr float EPS_ = 1e-5f;

// ---------------- scratch layout (floats) ----------------
static constexpr int OFF_XN = 0;                  // [B,D]   layernorm output
static constexpr int OFF_XT = OFF_XN + B_*D_;     // [B,P]   up-left
static constexpr int OFF_XC = OFF_XT + B_*P_;     // [B,P]   conv+silu
static constexpr int OFF_RS = OFF_XC + B_*P_;     // [B,HID] silu(r_t)
static constexpr int OFF_Q  = OFF_RS + B_*HID_;   // [B,HID]
static constexpr int OFF_K  = OFF_Q  + B_*HID_;   // [B,HID] (scaled)
static constexpr int OFF_V  = OFF_K  + B_*HID_;   // [B,HID]
static constexpr int OFF_O  = OFF_V  + B_*HID_;   // [B,HID] sigmoid(o)
static constexpr int OFF_IG = OFF_O  + B_*HID_;   // [B,H]
static constexpr int OFF_FG = OFF_IG + B_*H_;     // [B,H]
static constexpr int OFF_HN = OFF_FG + B_*H_;     // [B,HID] groupnormed h
static constexpr int OFF_O1 = OFF_HN + B_*HID_;   // [B,HID] (skip+hn)*rs
static constexpr int OFF_Y  = OFF_O1 + B_*HID_;   // [B,D]   down + x_n
static constexpr int SCRATCH_TOTAL = OFF_Y + B_*D_;

__device__ __align__(16) float g_s[SCRATCH_TOTAL];

// ---------------- utils ----------------
__device__ __forceinline__ float warp_sum(float v) {
#pragma unroll
    for (int o = 16; o > 0; o >>= 1) v += __shfl_xor_sync(0xffffffffu, v, o);
    return v;
}

// ---------------- LayerNorm: seq[B,D] -> g_s[XN] ----------------
__global__ void __launch_bounds__(256) ln_k(const float* __restrict__ seq,
                                            const float* __restrict__ g,
                                            const float* __restrict__ bt) {
    const int row = blockIdx.x, tid = threadIdx.x;
    const int wid = tid >> 5, lane = tid & 31;
    float4 x = reinterpret_cast<const float4*>(seq + row * D_)[tid];
    float s  = x.x + x.y + x.z + x.w;
    float q2 = x.x*x.x + x.y*x.y + x.z*x.z + x.w*x.w;
    s = warp_sum(s); q2 = warp_sum(q2);
    __shared__ float ssum[8], ssq[8];
    __shared__ float s_mu, s_inv;
    if (lane == 0) { ssum[wid] = s; ssq[wid] = q2; }
    __syncthreads();
    if (tid == 0) {
        float S = 0.f, Q = 0.f;
#pragma unroll
        for (int i = 0; i < 8; i++) { S += ssum[i]; Q += ssq[i]; }
        float mu = S * (1.0f / D_);
        float var = Q * (1.0f / D_) - mu * mu;
        s_mu = mu; s_inv = rsqrtf(var + EPS_);
    }
    __syncthreads();
    float4 gg = reinterpret_cast<const float4*>(g)[tid];
    float4 bb = reinterpret_cast<const float4*>(bt)[tid];
    float4 o;
    o.x = (x.x - s_mu) * s_inv * gg.x + bb.x;
    o.y = (x.y - s_mu) * s_inv * gg.y + bb.y;
    o.z = (x.z - s_mu) * s_inv * gg.z + bb.z;
    o.w = (x.w - s_mu) * s_inv * gg.w + bb.w;
    reinterpret_cast<float4*>(g_s + OFF_XN + row * D_)[tid] = o;
}

// ---------------- generic SIMT GEMM:  C[m,n] = sum_k A[m,k]*W[n,k]  ----------------
// EPI: 0 none, 1 silu, 2 sigmoid, 4 (v+e1)*e2, 5 v+e1   (bias added, then *scale, then EPI)
template<int BM, int BN, int TM, int TN, int EPI>
__global__ void __launch_bounds__(256) gemm_k(const float* __restrict__ A,
                                              const float* __restrict__ W,
                                              const float* __restrict__ bias,
                                              float* __restrict__ C,
                                              int Kd, int N,
                                              const float* __restrict__ e1,
                                              const float* __restrict__ e2,
                                              float scale) {
    __shared__ float As[16][BM + 4];
    __shared__ float Bs[16][BN + 4];
    const int tid = threadIdx.x;
    const int m0 = blockIdx.y * BM, n0 = blockIdx.x * BN;
    constexpr int NX = BN / TN;
    const int tx = tid % NX, ty = tid / NX;

    float acc[TM][TN];
#pragma unroll
    for (int i = 0; i < TM; i++)
#pragma unroll
        for (int j = 0; j < TN; j++) acc[i][j] = 0.f;

    for (int kt = 0; kt < Kd; kt += 16) {
        // load A tile (BM x 16), transposed into smem
        for (int i = tid; i < BM * 4; i += 256) {
            int row = i >> 2, kq = (i & 3) * 4;
            float4 va = *reinterpret_cast<const float4*>(A + (size_t)(m0 + row) * Kd + kt + kq);
            As[kq + 0][row] = va.x; As[kq + 1][row] = va.y;
            As[kq + 2][row] = va.z; As[kq + 3][row] = va.w;
        }
        // load W tile (BN x 16), transposed into smem
        for (int i = tid; i < BN * 4; i += 256) {
            int row = i >> 2, kq = (i & 3) * 4;
            float4 vb = *reinterpret_cast<const float4*>(W + (size_t)(n0 + row) * Kd + kt + kq);
            Bs[kq + 0][row] = vb.x; Bs[kq + 1][row] = vb.y;
            Bs[kq + 2][row] = vb.z; Bs[kq + 3][row] = vb.w;
        }
        __syncthreads();
#pragma unroll
        for (int kk = 0; kk < 16; kk++) {
            float a[TM], b[TN];
#pragma unroll
            for (int i = 0; i < TM; i++) a[i] = As[kk][ty * TM + i];
#pragma unroll
            for (int j = 0; j < TN; j++) b[j] = Bs[kk][tx * TN + j];
#pragma unroll
            for (int i = 0; i < TM; i++)
#pragma unroll
                for (int j = 0; j < TN; j++) acc[i][j] = fmaf(a[i], b[j], acc[i][j]);
        }
        __syncthreads();
    }

#pragma unroll
    for (int i = 0; i < TM; i++) {
        const int m = m0 + ty * TM + i;
#pragma unroll
        for (int j = 0; j < TN; j++) {
            const int n = n0 + tx * TN + j;
            float v = acc[i][j];
            if (bias) v += bias[n];
            v *= scale;
            const size_t idx = (size_t)m * N + n;
            if (EPI == 1) v = v / (1.f + expf(-v));             // silu
            else if (EPI == 2) v = 1.f / (1.f + expf(-v));      // sigmoid
            else if (EPI == 4) v = (v + e1[idx]) * e2[idx];     // (skip+hn)*silu(r)
            else if (EPI == 5) v = v + e1[idx];                 // + residual
            C[idx] = v;
        }
    }
}

// ---------------- causal conv (K=4) + silu: xt -> xc ----------------
__global__ void __launch_bounds__(256) conv_k(const float* __restrict__ cw,
                                              const float* __restrict__ cb) {
    const int idx = blockIdx.x * 256 + threadIdx.x;          // < B*P exactly
    const int b = idx >> 11, p = idx & (P_ - 1);
    const float* xt = g_s + OFF_XT + (size_t)b * P_;
    float v = cb[0];
    if (p >= 3) v = fmaf(cw[0], xt[p - 3], v);
    if (p >= 2) v = fmaf(cw[1], xt[p - 2], v);
    if (p >= 1) v = fmaf(cw[2], xt[p - 1], v);
    v = fmaf(cw[3], xt[p], v);
    v = v / (1.f + expf(-v));                                 // silu
    g_s[OFF_XC + idx] = v;
}

// ---------------- gates: i_t, f_t, m_t, i_g, f_g  (warp per head) ----------------
__global__ void __launch_bounds__(256) gates_k(const float* __restrict__ W_i,
                                               const float* __restrict__ b_i,
                                               const float* __restrict__ W_f,
                                               const float* __restrict__ b_f,
                                               const float* __restrict__ m_tm1,
                                               float* __restrict__ out_m) {
    const int b = blockIdx.x;
    const int h = threadIdx.x >> 5, l = threadIdx.x & 31;
    const float* xc = g_s + OFF_XC + (size_t)b * P_;
    const float* wi = W_i + (size_t)h * P_;
    const float* wf = W_f + (size_t)h * P_;
    float ai = 0.f, af = 0.f;
    for (int j = l; j < P_; j += 32) {
        float x = xc[j];
        ai = fmaf(x, wi[j], ai);
        af = fmaf(x, wf[j], af);
    }
    ai = warp_sum(ai); af = warp_sum(af);
    if (l == 0) {
        float it = ai + b_i[h];
        float ft = af + b_f[h];
        float mp = m_tm1[b * H_ + h];
        float mt = fmaxf(ft + mp, it);
        out_m[b * H_ + h] = mt;
        g_s[OFF_IG + b * H_ + h] = expf(it - mt);
        g_s[OFF_FG + b * H_ + h] = expf(ft - mt + mp);
    }
}

// ---------------- state update: c_t, n_t, num, den, h, GroupNorm (1 pass over c) ----
__global__ void __launch_bounds__(256) state_k(const float* __restrict__ c_tm1,
                                               const float* __restrict__ n_tm1,
                                               const float* __restrict__ gn_g,
                                               const float* __restrict__ gn_b,
                                               float* __restrict__ out_c,
                                               float* __restrict__ out_n) {
    const int bh = blockIdx.x;
    const int b = bh >> 3, h = bh & 7;
    const int tid = threadIdx.x;
    __shared__ float qs[HD_], ks[HD_], vs[HD_], nums[HD_], tmp[HD_];
    __shared__ float s_den, s_mu, s_inv;

    const float fgv = g_s[OFF_FG + bh];
    const float igv = g_s[OFF_IG + bh];

    if (tid < HD_) {
        const int gi = b * HID_ + h * HD_ + tid;
        qs[tid] = g_s[OFF_Q + gi];
        ks[tid] = g_s[OFF_K + gi];
        vs[tid] = g_s[OFF_V + gi];
    }
    __syncthreads();

    // n_t and den = max(n_t . q, 1)
    if (tid < HD_) {
        float nn = fmaf(fgv, n_tm1[(size_t)bh * HD_ + tid], igv * ks[tid]);
        out_n[(size_t)bh * HD_ + tid] = nn;
        tmp[tid] = nn * qs[tid];
    }
    __syncthreads();
    if (tid < 32) {
        float ssum = tmp[tid] + tmp[tid + 32] + tmp[tid + 64] + tmp[tid + 96];
        ssum = warp_sum(ssum);
        if (tid == 0) s_den = fmaxf(ssum, 1.0f);
    }
    __syncthreads();

    // c_t = f*c_old + i*v k^T ; num[d] = c_t[d,:] . q   (warp per 16 rows)
    const int w = tid >> 5, l = tid & 31;
    const size_t cbase = (size_t)bh * HD_ * HD_;
    for (int dd = 0; dd < 16; dd++) {
        const int d = w * 16 + dd;
        const float vd = vs[d] * igv;
        const size_t rb = cbase + (size_t)d * HD_;
        float acc = 0.f;
#pragma unroll
        for (int pp = 0; pp < 4; pp++) {
            const int p = l + 32 * pp;
            float cn = fmaf(fgv, c_tm1[rb + p], vd * ks[p]);
            out_c[rb + p] = cn;
            acc = fmaf(cn, qs[p], acc);
        }
        acc = warp_sum(acc);
        if (l == 0) nums[d] = acc;
    }
    __syncthreads();

    // h = sigmoid(o) * num/den, then GroupNorm over the 128 dims of this head
    if (tid < HD_) {
        float hv = g_s[OFF_O + b * HID_ + h * HD_ + tid] * nums[tid] / s_den;
        tmp[tid] = hv;
    }
    __syncthreads();
    if (tid < 32) {
        float ssum = 0.f, ssq = 0.f;
#pragma unroll
        for (int pp = 0; pp < 4; pp++) {
            float x = tmp[tid + 32 * pp];
            ssum += x; ssq += x * x;
        }
        ssum = warp_sum(ssum); ssq = warp_sum(ssq);
        if (tid == 0) {
            float mu = ssum * (1.0f / HD_);
            float var = ssq * (1.0f / HD_) - mu * mu;
            s_mu = mu; s_inv = rsqrtf(var + EPS_);
        }
    }
    __syncthreads();
    if (tid < HD_) {
        const int gi = h * HD_ + tid;
        g_s[OFF_HN + b * HID_ + gi] = (tmp[tid] - s_mu) * s_inv * gn_g[gi] + gn_b[gi];
    }
}

// ---------------- launch ----------------
extern "C" void kernel_launch(void* const* d_in, const int* in_sizes, int n_in,
                              void* d_out, int out_size) {
    const float* seq    = (const float*)d_in[0];
    const float* c_tm1  = (const float*)d_in[1];
    const float* n_tm1  = (const float*)d_in[2];
    const float* m_tm1  = (const float*)d_in[3];
    const float* ln_g   = (const float*)d_in[4];
    const float* ln_b   = (const float*)d_in[5];
    const float* gn_g   = (const float*)d_in[6];
    const float* gn_b   = (const float*)d_in[7];
    const float* W_upl  = (const float*)d_in[8];
    const float* b_upl  = (const float*)d_in[9];
    const float* W_upr  = (const float*)d_in[10];
    const float* b_upr  = (const float*)d_in[11];
    const float* W_down = (const float*)d_in[12];
    const float* b_down = (const float*)d_in[13];
    const float* W_last = (const float*)d_in[14];
    const float* b_last = (const float*)d_in[15];
    const float* conv_w = (const float*)d_in[16];
    const float* conv_b = (const float*)d_in[17];
    const float* W_skip = (const float*)d_in[18];
    const float* W_i    = (const float*)d_in[19];
    const float* b_i    = (const float*)d_in[20];
    const float* W_f    = (const float*)d_in[21];
    const float* b_f    = (const float*)d_in[22];
    const float* W_o    = (const float*)d_in[23];
    const float* b_o    = (const float*)d_in[24];
    const float* W_q    = (const float*)d_in[25];
    const float* b_q    = (const float*)d_in[26];
    const float* W_k    = (const float*)d_in[27];
    const float* b_k    = (const float*)d_in[28];
    const float* W_v    = (const float*)d_in[29];
    const float* b_v    = (const float*)d_in[30];

    float* out       = (float*)d_out;
    float* out_final = out;                                    // [B,O]
    float* out_c     = out + (size_t)B_ * O_;                  // [B,H,HD,HD]
    float* out_n     = out_c + (size_t)B_ * H_ * HD_ * HD_;    // [B,H,HD]
    float* out_m     = out_n + (size_t)B_ * H_ * HD_;          // [B,H]

    void* sp = nullptr;
    cudaGetSymbolAddress(&sp, g_s);
    float* s = (float*)sp;

    const float kscale = 0.08838834764831843f;                 // 1/sqrt(128)

    // 1) input LayerNorm
    ln_k<<<B_, 256>>>(seq, ln_g, ln_b);
    // 2) up-projections
    gemm_k<64,64,4,4,0><<<dim3(P_/64, B_/64), 256>>>(s+OFF_XN, W_upl, b_upl, s+OFF_XT, D_, P_, nullptr, nullptr, 1.f);
    gemm_k<32,64,2,4,1><<<dim3(HID_/64, B_/32), 256>>>(s+OFF_XN, W_upr, b_upr, s+OFF_RS, D_, HID_, nullptr, nullptr, 1.f);
    // 3) causal conv + silu
    conv_k<<<(B_*P_)/256, 256>>>(conv_w, conv_b);
    // 4) projections
    gemm_k<32,64,2,4,0><<<dim3(HID_/64, B_/32), 256>>>(s+OFF_XC, W_q, b_q, s+OFF_Q, P_, HID_, nullptr, nullptr, 1.f);
    gemm_k<32,64,2,4,0><<<dim3(HID_/64, B_/32), 256>>>(s+OFF_XC, W_k, b_k, s+OFF_K, P_, HID_, nullptr, nullptr, kscale);
    gemm_k<32,64,2,4,0><<<dim3(HID_/64, B_/32), 256>>>(s+OFF_XT, W_v, b_v, s+OFF_V, P_, HID_, nullptr, nullptr, 1.f);
    gemm_k<32,64,2,4,2><<<dim3(HID_/64, B_/32), 256>>>(s+OFF_XT, W_o, b_o, s+OFF_O, P_, HID_, nullptr, nullptr, 1.f);
    // 5) i/f gates + stabilized exp
    gates_k<<<B_, 256>>>(W_i, b_i, W_f, b_f, m_tm1, out_m);
    // 6) state update + output gate + GroupNorm (single pass over c)
    state_k<<<B_*H_, 256>>>(c_tm1, n_tm1, gn_g, gn_b, out_c, out_n);
    // 7) skip-GEMM fused: (x_c@W_skip^T + hn) * silu(r)
    gemm_k<32,64,2,4,4><<<dim3(HID_/64, B_/32), 256>>>(s+OFF_XC, W_skip, nullptr, s+OFF_O1, P_, HID_, s+OFF_HN, s+OFF_RS, 1.f);
    // 8) down-GEMM fused residual: +x_n
    gemm_k<32,64,2,4,5><<<dim3(D_/64, B_/32), 256>>>(s+OFF_O1, W_down, b_down, s+OFF_Y, HID_, D_, s+OFF_XN, nullptr, 1.f);
    // 9) final projection -> d_out
    gemm_k<32,64,2,4,0><<<dim3(O_/64, B_/32), 256>>>(s+OFF_Y, W_last, b_last, out_final, D_, O_, nullptr, nullptr, 1.f);
}

// round 4
// speedup vs baseline: 1.0916x; 1.0916x over previous
#include <cuda_runtime.h>
#include <math.h>

// ---------------- problem constants ----------------
static constexpr int B_   = 256;
static constexpr int D_   = 1024;
static constexpr int H_   = 8;
static constexpr int HD_  = 128;
static constexpr int P_   = 2048;
static constexpr int HID_ = 1024;   // H*HD
static constexpr int O_   = 1024;
static constexpr float EPS_ = 1e-5f;

// ---------------- scratch layout (floats) ----------------
static constexpr int OFF_XN = 0;                  // [B,D]   layernorm output
static constexpr int OFF_XT = OFF_XN + B_*D_;     // [B,P]   up-left
static constexpr int OFF_XC = OFF_XT + B_*P_;     // [B,P]   conv+silu
static constexpr int OFF_RS = OFF_XC + B_*P_;     // [B,HID] silu(r_t)
static constexpr int OFF_Q  = OFF_RS + B_*HID_;   // [B,HID]
static constexpr int OFF_K  = OFF_Q  + B_*HID_;   // [B,HID] (scaled)
static constexpr int OFF_V  = OFF_K  + B_*HID_;   // [B,HID]
static constexpr int OFF_O  = OFF_V  + B_*HID_;   // [B,HID] sigmoid(o)
static constexpr int OFF_IG = OFF_O  + B_*HID_;   // [B,H]
static constexpr int OFF_FG = OFF_IG + B_*H_;     // [B,H]
static constexpr int OFF_HN = OFF_FG + B_*H_;     // [B,HID] groupnormed h
static constexpr int OFF_O1 = OFF_HN + B_*HID_;   // [B,HID] (skip+hn)*rs
static constexpr int OFF_Y  = OFF_O1 + B_*HID_;   // [B,D]   down + x_n
static constexpr int SCRATCH_TOTAL = OFF_Y + B_*D_;

__device__ __align__(16) float g_s[SCRATCH_TOTAL];

// ---------------- utils ----------------
__device__ __forceinline__ float warp_sum(float v) {
#pragma unroll
    for (int o = 16; o > 0; o >>= 1) v += __shfl_xor_sync(0xffffffffu, v, o);
    return v;
}

// ---------------- LayerNorm: seq[B,D] -> g_s[XN] ----------------
__global__ void __launch_bounds__(256) ln_k(const float* __restrict__ seq,
                                            const float* __restrict__ g,
                                            const float* __restrict__ bt) {
    const int row = blockIdx.x, tid = threadIdx.x;
    const int wid = tid >> 5, lane = tid & 31;
    float4 x = reinterpret_cast<const float4*>(seq + row * D_)[tid];
    float s  = x.x + x.y + x.z + x.w;
    float q2 = x.x*x.x + x.y*x.y + x.z*x.z + x.w*x.w;
    s = warp_sum(s); q2 = warp_sum(q2);
    __shared__ float ssum[8], ssq[8];
    __shared__ float s_mu, s_inv;
    if (lane == 0) { ssum[wid] = s; ssq[wid] = q2; }
    __syncthreads();
    if (tid == 0) {
        float S = 0.f, Q = 0.f;
#pragma unroll
        for (int i = 0; i < 8; i++) { S += ssum[i]; Q += ssq[i]; }
        float mu = S * (1.0f / D_);
        float var = Q * (1.0f / D_) - mu * mu;
        s_mu = mu; s_inv = rsqrtf(var + EPS_);
    }
    __syncthreads();
    float4 gg = reinterpret_cast<const float4*>(g)[tid];
    float4 bb = reinterpret_cast<const float4*>(bt)[tid];
    float4 o;
    o.x = (x.x - s_mu) * s_inv * gg.x + bb.x;
    o.y = (x.y - s_mu) * s_inv * gg.y + bb.y;
    o.z = (x.z - s_mu) * s_inv * gg.z + bb.z;
    o.w = (x.w - s_mu) * s_inv * gg.w + bb.w;
    reinterpret_cast<float4*>(g_s + OFF_XN + row * D_)[tid] = o;
}

// ---------------- SIMT GEMM v2: double-buffered, vectorized fragments ----------
//  C[m,n] = (sum_k A[m,k]*W[n,k] + bias[n]) * scale, then EPI
//  EPI: 0 none, 1 silu, 2 sigmoid, 4 (v+e1)*e2, 5 v+e1
//  256 threads. TM in {2,4} (float2/float4 a-frag), TN in {2,4}.
template<int BM, int BN, int TM, int TN, int EPI>
__global__ void __launch_bounds__(256) gemm2_k(const float* __restrict__ A,
                                               const float* __restrict__ W,
                                               const float* __restrict__ bias,
                                               float* __restrict__ C,
                                               int Kd, int N,
                                               const float* __restrict__ e1,
                                               const float* __restrict__ e2,
                                               float scale) {
    constexpr int KC = 16;
    constexpr int LDA = BM + 4;
    constexpr int LDB = BN + 4;
    __shared__ float As[2][KC][LDA];
    __shared__ float Bs[2][KC][LDB];

    const int tid = threadIdx.x;
    const int m0 = blockIdx.y * BM, n0 = blockIdx.x * BN;
    constexpr int NX = BN / TN;             // threads along n
    const int tx = tid % NX, ty = tid / NX;

    // ---- global-load assignments (float4 granularity) ----
    constexpr int A_F4 = BM * KC / 4;       // <= 256
    constexpr int B_F4 = BN * KC / 4;       // 256 for BN=64
    const bool hasA = (A_F4 == 256) || (tid < A_F4);
    const bool hasB = (B_F4 == 256) || (tid < B_F4);
    const int arow = tid >> 2, akq = (tid & 3) * 4;
    const int brow = tid >> 2, bkq = (tid & 3) * 4;
    const float* Aptr = A + (size_t)(m0 + arow) * Kd + akq;
    const float* Wptr = W + (size_t)(n0 + brow) * Kd + bkq;

    float4 pa = make_float4(0.f,0.f,0.f,0.f), pb = make_float4(0.f,0.f,0.f,0.f);
    const int ntiles = Kd / KC;

    // prologue: load tile 0, stage to buffer 0
    if (hasA) pa = *reinterpret_cast<const float4*>(Aptr);
    if (hasB) pb = *reinterpret_cast<const float4*>(Wptr);
    if (hasA) {
        As[0][akq+0][arow] = pa.x; As[0][akq+1][arow] = pa.y;
        As[0][akq+2][arow] = pa.z; As[0][akq+3][arow] = pa.w;
    }
    if (hasB) {
        Bs[0][bkq+0][brow] = pb.x; Bs[0][bkq+1][brow] = pb.y;
        Bs[0][bkq+2][brow] = pb.z; Bs[0][bkq+3][brow] = pb.w;
    }
    __syncthreads();

    float acc[TM][TN];
#pragma unroll
    for (int i = 0; i < TM; i++)
#pragma unroll
        for (int j = 0; j < TN; j++) acc[i][j] = 0.f;

    int buf = 0;
    for (int t = 0; t < ntiles; t++) {
        // prefetch next tile into registers
        if (t + 1 < ntiles) {
            const int off = (t + 1) * KC;
            if (hasA) pa = *reinterpret_cast<const float4*>(Aptr + off);
            if (hasB) pb = *reinterpret_cast<const float4*>(Wptr + off);
        }
        // compute on current buffer
        const float* Ac = &As[buf][0][0];
        const float* Bc = &Bs[buf][0][0];
#pragma unroll
        for (int kk = 0; kk < KC; kk++) {
            float a[TM], b[TN];
            if (TM == 4) {
                float4 a4 = *reinterpret_cast<const float4*>(Ac + kk * LDA + ty * TM);
                a[0]=a4.x; a[1]=a4.y; a[2]=a4.z; a[3]=a4.w;
            } else {
                float2 a2 = *reinterpret_cast<const float2*>(Ac + kk * LDA + ty * TM);
                a[0]=a2.x; a[1]=a2.y;
            }
            if (TN == 4) {
                float4 b4 = *reinterpret_cast<const float4*>(Bc + kk * LDB + tx * TN);
                b[0]=b4.x; b[1]=b4.y; b[2]=b4.z; b[3]=b4.w;
            } else {
                float2 b2 = *reinterpret_cast<const float2*>(Bc + kk * LDB + tx * TN);
                b[0]=b2.x; b[1]=b2.y;
            }
#pragma unroll
            for (int i = 0; i < TM; i++)
#pragma unroll
                for (int j = 0; j < TN; j++) acc[i][j] = fmaf(a[i], b[j], acc[i][j]);
        }
        // stage prefetched tile into other buffer
        if (t + 1 < ntiles) {
            const int nb = buf ^ 1;
            if (hasA) {
                As[nb][akq+0][arow] = pa.x; As[nb][akq+1][arow] = pa.y;
                As[nb][akq+2][arow] = pa.z; As[nb][akq+3][arow] = pa.w;
            }
            if (hasB) {
                Bs[nb][bkq+0][brow] = pb.x; Bs[nb][bkq+1][brow] = pb.y;
                Bs[nb][bkq+2][brow] = pb.z; Bs[nb][bkq+3][brow] = pb.w;
            }
            __syncthreads();
            buf = nb;
        }
    }

    // epilogue
#pragma unroll
    for (int i = 0; i < TM; i++) {
        const int m = m0 + ty * TM + i;
#pragma unroll
        for (int j = 0; j < TN; j++) {
            const int n = n0 + tx * TN + j;
            float v = acc[i][j];
            if (bias) v += bias[n];
            v *= scale;
            const size_t idx = (size_t)m * N + n;
            if (EPI == 1) v = v / (1.f + expf(-v));             // silu
            else if (EPI == 2) v = 1.f / (1.f + expf(-v));      // sigmoid
            else if (EPI == 4) v = (v + e1[idx]) * e2[idx];     // (skip+hn)*silu(r)
            else if (EPI == 5) v = v + e1[idx];                 // + residual
            C[idx] = v;
        }
    }
}

// ---------------- causal conv (K=4) + silu: xt -> xc ----------------
__global__ void __launch_bounds__(256) conv_k(const float* __restrict__ cw,
                                              const float* __restrict__ cb) {
    const int idx = blockIdx.x * 256 + threadIdx.x;          // < B*P exactly
    const int b = idx >> 11, p = idx & (P_ - 1);
    const float* xt = g_s + OFF_XT + (size_t)b * P_;
    float v = cb[0];
    if (p >= 3) v = fmaf(cw[0], xt[p - 3], v);
    if (p >= 2) v = fmaf(cw[1], xt[p - 2], v);
    if (p >= 1) v = fmaf(cw[2], xt[p - 1], v);
    v = fmaf(cw[3], xt[p], v);
    v = v / (1.f + expf(-v));                                 // silu
    g_s[OFF_XC + idx] = v;
}

// ---------------- gates: i_t, f_t, m_t, i_g, f_g  (warp per head) ----------------
__global__ void __launch_bounds__(256) gates_k(const float* __restrict__ W_i,
                                               const float* __restrict__ b_i,
                                               const float* __restrict__ W_f,
                                               const float* __restrict__ b_f,
                                               const float* __restrict__ m_tm1,
                                               float* __restrict__ out_m) {
    const int b = blockIdx.x;
    const int h = threadIdx.x >> 5, l = threadIdx.x & 31;
    const float4* xc = reinterpret_cast<const float4*>(g_s + OFF_XC + (size_t)b * P_);
    const float4* wi = reinterpret_cast<const float4*>(W_i + (size_t)h * P_);
    const float4* wf = reinterpret_cast<const float4*>(W_f + (size_t)h * P_);
    float ai = 0.f, af = 0.f;
    for (int j = l; j < P_ / 4; j += 32) {
        float4 x = xc[j], vi = wi[j], vf = wf[j];
        ai = fmaf(x.x, vi.x, fmaf(x.y, vi.y, fmaf(x.z, vi.z, fmaf(x.w, vi.w, ai))));
        af = fmaf(x.x, vf.x, fmaf(x.y, vf.y, fmaf(x.z, vf.z, fmaf(x.w, vf.w, af))));
    }
    ai = warp_sum(ai); af = warp_sum(af);
    if (l == 0) {
        float it = ai + b_i[h];
        float ft = af + b_f[h];
        float mp = m_tm1[b * H_ + h];
        float mt = fmaxf(ft + mp, it);
        out_m[b * H_ + h] = mt;
        g_s[OFF_IG + b * H_ + h] = expf(it - mt);
        g_s[OFF_FG + b * H_ + h] = expf(ft - mt + mp);
    }
}

// ---------------- state update: c_t, n_t, num, den, h, GroupNorm (1 pass over c) ----
__global__ void __launch_bounds__(256) state_k(const float* __restrict__ c_tm1,
                                               const float* __restrict__ n_tm1,
                                               const float* __restrict__ gn_g,
                                               const float* __restrict__ gn_b,
                                               float* __restrict__ out_c,
                                               float* __restrict__ out_n) {
    const int bh = blockIdx.x;
    const int b = bh >> 3, h = bh & 7;
    const int tid = threadIdx.x;
    __shared__ __align__(16) float qs[HD_], ks[HD_], vs[HD_], nums[HD_], tmp[HD_];
    __shared__ float s_den, s_mu, s_inv;

    const float fgv = g_s[OFF_FG + bh];
    const float igv = g_s[OFF_IG + bh];

    if (tid < HD_) {
        const int gi = b * HID_ + h * HD_ + tid;
        qs[tid] = g_s[OFF_Q + gi];
        ks[tid] = g_s[OFF_K + gi];
        vs[tid] = g_s[OFF_V + gi];
    }
    __syncthreads();

    // n_t and den = max(n_t . q, 1)
    if (tid < HD_) {
        float nn = fmaf(fgv, n_tm1[(size_t)bh * HD_ + tid], igv * ks[tid]);
        out_n[(size_t)bh * HD_ + tid] = nn;
        tmp[tid] = nn * qs[tid];
    }
    __syncthreads();
    if (tid < 32) {
        float ssum = tmp[tid] + tmp[tid + 32] + tmp[tid + 64] + tmp[tid + 96];
        ssum = warp_sum(ssum);
        if (tid == 0) s_den = fmaxf(ssum, 1.0f);
    }
    __syncthreads();

    // c_t = f*c_old + i*v k^T ; num[d] = c_t[d,:] . q   (warp per 16 rows, float4)
    const int w = tid >> 5, l = tid & 31;
    const size_t cbase = (size_t)bh * HD_ * HD_;
    const float4 k4 = reinterpret_cast<const float4*>(ks)[l];
    const float4 q4 = reinterpret_cast<const float4*>(qs)[l];
#pragma unroll 4
    for (int dd = 0; dd < 16; dd++) {
        const int d = w * 16 + dd;
        const float vd = vs[d] * igv;
        const size_t rb = cbase + (size_t)d * HD_;
        float4 c4 = reinterpret_cast<const float4*>(c_tm1 + rb)[l];
        float4 cn;
        cn.x = fmaf(fgv, c4.x, vd * k4.x);
        cn.y = fmaf(fgv, c4.y, vd * k4.y);
        cn.z = fmaf(fgv, c4.z, vd * k4.z);
        cn.w = fmaf(fgv, c4.w, vd * k4.w);
        reinterpret_cast<float4*>(out_c + rb)[l] = cn;
        float acc = cn.x*q4.x + cn.y*q4.y + cn.z*q4.z + cn.w*q4.w;
        acc = warp_sum(acc);
        if (l == 0) nums[d] = acc;
    }
    __syncthreads();

    // h = sigmoid(o) * num/den, then GroupNorm over the 128 dims of this head
    if (tid < HD_) {
        float hv = g_s[OFF_O + b * HID_ + h * HD_ + tid] * nums[tid] / s_den;
        tmp[tid] = hv;
    }
    __syncthreads();
    if (tid < 32) {
        float ssum = 0.f, ssq = 0.f;
#pragma unroll
        for (int pp = 0; pp < 4; pp++) {
            float x = tmp[tid + 32 * pp];
            ssum += x; ssq += x * x;
        }
        ssum = warp_sum(ssum); ssq = warp_sum(ssq);
        if (tid == 0) {
            float mu = ssum * (1.0f / HD_);
            float var = ssq * (1.0f / HD_) - mu * mu;
            s_mu = mu; s_inv = rsqrtf(var + EPS_);
        }
    }
    __syncthreads();
    if (tid < HD_) {
        const int gi = h * HD_ + tid;
        g_s[OFF_HN + b * HID_ + gi] = (tmp[tid] - s_mu) * s_inv * gn_g[gi] + gn_b[gi];
    }
}

// ---------------- launch ----------------
extern "C" void kernel_launch(void* const* d_in, const int* in_sizes, int n_in,
                              void* d_out, int out_size) {
    const float* seq    = (const float*)d_in[0];
    const float* c_tm1  = (const float*)d_in[1];
    const float* n_tm1  = (const float*)d_in[2];
    const float* m_tm1  = (const float*)d_in[3];
    const float* ln_g   = (const float*)d_in[4];
    const float* ln_b   = (const float*)d_in[5];
    const float* gn_g   = (const float*)d_in[6];
    const float* gn_b   = (const float*)d_in[7];
    const float* W_upl  = (const float*)d_in[8];
    const float* b_upl  = (const float*)d_in[9];
    const float* W_upr  = (const float*)d_in[10];
    const float* b_upr  = (const float*)d_in[11];
    const float* W_down = (const float*)d_in[12];
    const float* b_down = (const float*)d_in[13];
    const float* W_last = (const float*)d_in[14];
    const float* b_last = (const float*)d_in[15];
    const float* conv_w = (const float*)d_in[16];
    const float* conv_b = (const float*)d_in[17];
    const float* W_skip = (const float*)d_in[18];
    const float* W_i    = (const float*)d_in[19];
    const float* b_i    = (const float*)d_in[20];
    const float* W_f    = (const float*)d_in[21];
    const float* b_f    = (const float*)d_in[22];
    const float* W_o    = (const float*)d_in[23];
    const float* b_o    = (const float*)d_in[24];
    const float* W_q    = (const float*)d_in[25];
    const float* b_q    = (const float*)d_in[26];
    const float* W_k    = (const float*)d_in[27];
    const float* b_k    = (const float*)d_in[28];
    const float* W_v    = (const float*)d_in[29];
    const float* b_v    = (const float*)d_in[30];

    float* out       = (float*)d_out;
    float* out_final = out;                                    // [B,O]
    float* out_c     = out + (size_t)B_ * O_;                  // [B,H,HD,HD]
    float* out_n     = out_c + (size_t)B_ * H_ * HD_ * HD_;    // [B,H,HD]
    float* out_m     = out_n + (size_t)B_ * H_ * HD_;          // [B,H]

    void* sp = nullptr;
    cudaGetSymbolAddress(&sp, g_s);
    float* s = (float*)sp;

    const float kscale = 0.08838834764831843f;                 // 1/sqrt(128)

    // 1) input LayerNorm
    ln_k<<<B_, 256>>>(seq, ln_g, ln_b);
    // 2) up-projections
    gemm2_k<64,64,4,4,0><<<dim3(P_/64, B_/64), 256>>>(s+OFF_XN, W_upl, b_upl, s+OFF_XT, D_, P_, nullptr, nullptr, 1.f);
    gemm2_k<32,64,4,2,1><<<dim3(HID_/64, B_/32), 256>>>(s+OFF_XN, W_upr, b_upr, s+OFF_RS, D_, HID_, nullptr, nullptr, 1.f);
    // 3) causal conv + silu
    conv_k<<<(B_*P_)/256, 256>>>(conv_w, conv_b);
    // 4) projections
    gemm2_k<32,64,4,2,0><<<dim3(HID_/64, B_/32), 256>>>(s+OFF_XC, W_q, b_q, s+OFF_Q, P_, HID_, nullptr, nullptr, 1.f);
    gemm2_k<32,64,4,2,0><<<dim3(HID_/64, B_/32), 256>>>(s+OFF_XC, W_k, b_k, s+OFF_K, P_, HID_, nullptr, nullptr, kscale);
    gemm2_k<32,64,4,2,0><<<dim3(HID_/64, B_/32), 256>>>(s+OFF_XT, W_v, b_v, s+OFF_V, P_, HID_, nullptr, nullptr, 1.f);
    gemm2_k<32,64,4,2,2><<<dim3(HID_/64, B_/32), 256>>>(s+OFF_XT, W_o, b_o, s+OFF_O, P_, HID_, nullptr, nullptr, 1.f);
    // 5) i/f gates + stabilized exp
    gates_k<<<B_, 256>>>(W_i, b_i, W_f, b_f, m_tm1, out_m);
    // 6) state update + output gate + GroupNorm (single pass over c)
    state_k<<<B_*H_, 256>>>(c_tm1, n_tm1, gn_g, gn_b, out_c, out_n);
    // 7) skip-GEMM fused: (x_c@W_skip^T + hn) * silu(r)
    gemm2_k<32,64,4,2,4><<<dim3(HID_/64, B_/32), 256>>>(s+OFF_XC, W_skip, nullptr, s+OFF_O1, P_, HID_, s+OFF_HN, s+OFF_RS, 1.f);
    // 8) down-GEMM fused residual: +x_n
    gemm2_k<32,64,4,2,5><<<dim3(D_/64, B_/32), 256>>>(s+OFF_O1, W_down, b_down, s+OFF_Y, HID_, D_, s+OFF_XN, nullptr, 1.f);
    // 9) final projection -> d_out
    gemm2_k<32,64,4,2,0><<<dim3(O_/64, B_/32), 256>>>(s+OFF_Y, W_last, b_last, out_final, D_, O_, nullptr, nullptr, 1.f);
}

// round 6
// speedup vs baseline: 1.7700x; 1.6215x over previous
#include <cuda_runtime.h>
#include <math.h>

// ---------------- problem constants ----------------
static constexpr int B_   = 256;
static constexpr int D_   = 1024;
static constexpr int H_   = 8;
static constexpr int HD_  = 128;
static constexpr int P_   = 2048;
static constexpr int HID_ = 1024;   // H*HD
static constexpr int O_   = 1024;
static constexpr float EPS_ = 1e-5f;

// ---------------- scratch layout (floats) ----------------
static constexpr int OFF_XN = 0;                  // [B,D]   layernorm output
static constexpr int OFF_XT = OFF_XN + B_*D_;     // [B,P]   up-left
static constexpr int OFF_XC = OFF_XT + B_*P_;     // [B,P]   conv+silu
static constexpr int OFF_RS = OFF_XC + B_*P_;     // [B,HID] silu(r_t)
static constexpr int OFF_Q  = OFF_RS + B_*HID_;   // [B,HID]
static constexpr int OFF_K  = OFF_Q  + B_*HID_;   // [B,HID] (scaled)   (Q,K,V,O contiguous)
static constexpr int OFF_V  = OFF_K  + B_*HID_;   // [B,HID]
static constexpr int OFF_O  = OFF_V  + B_*HID_;   // [B,HID] sigmoid(o)
static constexpr int OFF_IG = OFF_O  + B_*HID_;   // [B,H]
static constexpr int OFF_FG = OFF_IG + B_*H_;     // [B,H]
static constexpr int OFF_HN = OFF_FG + B_*H_;     // [B,HID] groupnormed h
static constexpr int OFF_O1 = OFF_HN + B_*HID_;   // [B,HID] (skip+hn)*rs
static constexpr int OFF_Y  = OFF_O1 + B_*HID_;   // [B,D]   down + x_n
static constexpr int SCRATCH_TOTAL = OFF_Y + B_*D_;

__device__ __align__(16) float g_s[SCRATCH_TOTAL];

// ---------------- utils ----------------
__device__ __forceinline__ float warp_sum(float v) {
#pragma unroll
    for (int o = 16; o > 0; o >>= 1) v += __shfl_xor_sync(0xffffffffu, v, o);
    return v;
}

// ---------------- LayerNorm: seq[B,D] -> g_s[XN] ----------------
__global__ void __launch_bounds__(256) ln_k(const float* __restrict__ seq,
                                            const float* __restrict__ g,
                                            const float* __restrict__ bt) {
    const int row = blockIdx.x, tid = threadIdx.x;
    const int wid = tid >> 5, lane = tid & 31;
    float4 x = reinterpret_cast<const float4*>(seq + row * D_)[tid];
    float s  = x.x + x.y + x.z + x.w;
    float q2 = x.x*x.x + x.y*x.y + x.z*x.z + x.w*x.w;
    s = warp_sum(s); q2 = warp_sum(q2);
    __shared__ float ssum[8], ssq[8];
    __shared__ float s_mu, s_inv;
    if (lane == 0) { ssum[wid] = s; ssq[wid] = q2; }
    __syncthreads();
    if (tid == 0) {
        float S = 0.f, Q = 0.f;
#pragma unroll
        for (int i = 0; i < 8; i++) { S += ssum[i]; Q += ssq[i]; }
        float mu = S * (1.0f / D_);
        float var = Q * (1.0f / D_) - mu * mu;
        s_mu = mu; s_inv = rsqrtf(var + EPS_);
    }
    __syncthreads();
    float4 gg = reinterpret_cast<const float4*>(g)[tid];
    float4 bb = reinterpret_cast<const float4*>(bt)[tid];
    float4 o;
    o.x = (x.x - s_mu) * s_inv * gg.x + bb.x;
    o.y = (x.y - s_mu) * s_inv * gg.y + bb.y;
    o.z = (x.z - s_mu) * s_inv * gg.z + bb.z;
    o.w = (x.w - s_mu) * s_inv * gg.w + bb.w;
    reinterpret_cast<float4*>(g_s + OFF_XN + row * D_)[tid] = o;
}

// ============================================================================
// GEMM core: KC=32 double-buffered, float4 fragments, RUNTIME epilogue select.
//  C[m,n] = (sum_k A[m,k]*W[n,k] + bias[n]) * scale, then EPI
//  epi: 0 none, 1 silu, 2 sigmoid, 4 (v+e1)*e2, 5 v+e1
//  BM=32 fixed (TM=4), 256 threads, KC=32. One instantiation per (BN,TN).
// ============================================================================
template<int BN, int TN>
__device__ __forceinline__ void gemm_core(const float* __restrict__ A,
                                          const float* __restrict__ W,
                                          const float* __restrict__ bias,
                                          float* __restrict__ C,
                                          int Kd, int N, int m0, int n0,
                                          const float* __restrict__ e1,
                                          const float* __restrict__ e2,
                                          float scale, int epi) {
    constexpr int BM = 32, TM = 4, KC = 32;
    constexpr int LDA = BM + 4;
    constexpr int LDB = BN + 4;
    constexpr int NB  = BN / 32;            // B float4 loads per thread
    __shared__ __align__(16) float As[2][KC][LDA];
    __shared__ __align__(16) float Bs[2][KC][LDB];

    const int tid = threadIdx.x;
    constexpr int NX = BN / TN;             // threads along n
    const int tx = tid % NX, ty = tid / NX;

    const int arow = tid >> 3;              // 0..31
    const int akq  = (tid & 7) * 4;         // 0,4,...,28
    const float* Aptr = A + (size_t)(m0 + arow) * Kd + akq;
    const float* Wptr[NB];
#pragma unroll
    for (int r = 0; r < NB; r++)
        Wptr[r] = W + (size_t)(n0 + arow + r * 32) * Kd + akq;

    const int ntiles = Kd / KC;

    // prologue: tile 0 -> buffer 0
    {
        float4 pa = *reinterpret_cast<const float4*>(Aptr);
        As[0][akq+0][arow] = pa.x; As[0][akq+1][arow] = pa.y;
        As[0][akq+2][arow] = pa.z; As[0][akq+3][arow] = pa.w;
#pragma unroll
        for (int r = 0; r < NB; r++) {
            float4 pb = *reinterpret_cast<const float4*>(Wptr[r]);
            const int br = arow + r * 32;
            Bs[0][akq+0][br] = pb.x; Bs[0][akq+1][br] = pb.y;
            Bs[0][akq+2][br] = pb.z; Bs[0][akq+3][br] = pb.w;
        }
    }
    __syncthreads();

    float acc[TM][TN];
#pragma unroll
    for (int i = 0; i < TM; i++)
#pragma unroll
        for (int j = 0; j < TN; j++) acc[i][j] = 0.f;

    int buf = 0;
    for (int t = 0; t < ntiles; t++) {
        float4 pa; float4 pb[NB];
        const bool more = (t + 1 < ntiles);
        if (more) {
            const int off = (t + 1) * KC;
            pa = *reinterpret_cast<const float4*>(Aptr + off);
#pragma unroll
            for (int r = 0; r < NB; r++)
                pb[r] = *reinterpret_cast<const float4*>(Wptr[r] + off);
        }
        const float* Ac = &As[buf][0][0];
        const float* Bc = &Bs[buf][0][0];
#pragma unroll
        for (int kk = 0; kk < KC; kk++) {
            float a[TM], b[TN];
            float4 a4 = *reinterpret_cast<const float4*>(Ac + kk * LDA + ty * TM);
            a[0]=a4.x; a[1]=a4.y; a[2]=a4.z; a[3]=a4.w;
            if (TN == 4) {
                float4 b4 = *reinterpret_cast<const float4*>(Bc + kk * LDB + tx * TN);
                b[0]=b4.x; b[1]=b4.y; b[2]=b4.z; b[3]=b4.w;
            } else {
                float2 b2 = *reinterpret_cast<const float2*>(Bc + kk * LDB + tx * TN);
                b[0]=b2.x; b[1]=b2.y;
            }
#pragma unroll
            for (int i = 0; i < TM; i++)
#pragma unroll
                for (int j = 0; j < TN; j++) acc[i][j] = fmaf(a[i], b[j], acc[i][j]);
        }
        if (more) {
            const int nb = buf ^ 1;
            As[nb][akq+0][arow] = pa.x; As[nb][akq+1][arow] = pa.y;
            As[nb][akq+2][arow] = pa.z; As[nb][akq+3][arow] = pa.w;
#pragma unroll
            for (int r = 0; r < NB; r++) {
                const int br = arow + r * 32;
                Bs[nb][akq+0][br] = pb[r].x; Bs[nb][akq+1][br] = pb[r].y;
                Bs[nb][akq+2][br] = pb[r].z; Bs[nb][akq+3][br] = pb[r].w;
            }
            __syncthreads();
            buf = nb;
        }
    }

    // epilogue (runtime select; executed once per output element)
#pragma unroll
    for (int i = 0; i < TM; i++) {
        const int m = m0 + ty * TM + i;
#pragma unroll
        for (int j = 0; j < TN; j++) {
            const int n = n0 + tx * TN + j;
            float v = acc[i][j];
            if (bias) v += bias[n];
            v *= scale;
            const size_t idx = (size_t)m * N + n;
            if (epi == 1) v = v / (1.f + expf(-v));             // silu
            else if (epi == 2) v = 1.f / (1.f + expf(-v));      // sigmoid
            else if (epi == 4) v = (v + e1[idx]) * e2[idx];     // (skip+hn)*silu(r)
            else if (epi == 5) v = v + e1[idx];                 // + residual
            C[idx] = v;
        }
    }
}

// single GEMM wrapper
template<int BN, int TN>
__global__ void __launch_bounds__(256) gemm3_k(const float* __restrict__ A,
                                               const float* __restrict__ W,
                                               const float* __restrict__ bias,
                                               float* __restrict__ C,
                                               int Kd, int N,
                                               const float* __restrict__ e1,
                                               const float* __restrict__ e2,
                                               float scale, int epi) {
    gemm_core<BN, TN>(A, W, bias, C, Kd, N,
                      blockIdx.y * 32, blockIdx.x * BN, e1, e2, scale, epi);
}

// batched q/k/v/o GEMM: z selects operand set. A = xc for z<2, xt for z>=2.
// Outputs go to contiguous Q,K,V,O scratch. z==1 applies k-scale; z==3 sigmoid.
__global__ void __launch_bounds__(256) qkvo_k(const float* __restrict__ W_q,
                                              const float* __restrict__ b_q,
                                              const float* __restrict__ W_k,
                                              const float* __restrict__ b_k,
                                              const float* __restrict__ W_v,
                                              const float* __restrict__ b_v,
                                              const float* __restrict__ W_o,
                                              const float* __restrict__ b_o,
                                              float kscale) {
    const int z = blockIdx.z;
    const float* A = g_s + (z < 2 ? OFF_XC : OFF_XT);
    const float* W = (z == 0) ? W_q : (z == 1) ? W_k : (z == 2) ? W_v : W_o;
    const float* bias = (z == 0) ? b_q : (z == 1) ? b_k : (z == 2) ? b_v : b_o;
    float* C = g_s + OFF_Q + (size_t)z * B_ * HID_;
    const float scale = (z == 1) ? kscale : 1.0f;
    const int epi = (z == 3) ? 2 : 0;
    gemm_core<128, 4>(A, W, bias, C, P_, HID_, blockIdx.y * 32, blockIdx.x * 128,
                      nullptr, nullptr, scale, epi);
}

// ---------------- causal conv (K=4) + silu: xt -> xc ----------------
__global__ void __launch_bounds__(256) conv_k(const float* __restrict__ cw,
                                              const float* __restrict__ cb) {
    const int idx = blockIdx.x * 256 + threadIdx.x;          // < B*P exactly
    const int b = idx >> 11, p = idx & (P_ - 1);
    const float* xt = g_s + OFF_XT + (size_t)b * P_;
    float v = cb[0];
    if (p >= 3) v = fmaf(cw[0], xt[p - 3], v);
    if (p >= 2) v = fmaf(cw[1], xt[p - 2], v);
    if (p >= 1) v = fmaf(cw[2], xt[p - 1], v);
    v = fmaf(cw[3], xt[p], v);
    v = v / (1.f + expf(-v));                                 // silu
    g_s[OFF_XC + idx] = v;
}

// ---------------- gates: i_t, f_t, m_t, i_g, f_g  (warp per head) ----------------
__global__ void __launch_bounds__(256) gates_k(const float* __restrict__ W_i,
                                               const float* __restrict__ b_i,
                                               const float* __restrict__ W_f,
                                               const float* __restrict__ b_f,
                                               const float* __restrict__ m_tm1,
                                               float* __restrict__ out_m) {
    const int b = blockIdx.x;
    const int h = threadIdx.x >> 5, l = threadIdx.x & 31;
    const float4* xc = reinterpret_cast<const float4*>(g_s + OFF_XC + (size_t)b * P_);
    const float4* wi = reinterpret_cast<const float4*>(W_i + (size_t)h * P_);
    const float4* wf = reinterpret_cast<const float4*>(W_f + (size_t)h * P_);
    float ai = 0.f, af = 0.f;
    for (int j = l; j < P_ / 4; j += 32) {
        float4 x = xc[j], vi = wi[j], vf = wf[j];
        ai = fmaf(x.x, vi.x, fmaf(x.y, vi.y, fmaf(x.z, vi.z, fmaf(x.w, vi.w, ai))));
        af = fmaf(x.x, vf.x, fmaf(x.y, vf.y, fmaf(x.z, vf.z, fmaf(x.w, vf.w, af))));
    }
    ai = warp_sum(ai); af = warp_sum(af);
    if (l == 0) {
        float it = ai + b_i[h];
        float ft = af + b_f[h];
        float mp = m_tm1[b * H_ + h];
        float mt = fmaxf(ft + mp, it);
        out_m[b * H_ + h] = mt;
        g_s[OFF_IG + b * H_ + h] = expf(it - mt);
        g_s[OFF_FG + b * H_ + h] = expf(ft - mt + mp);
    }
}

// ---------------- state update: c_t, n_t, num, den, h, GroupNorm (1 pass over c) ----
__global__ void __launch_bounds__(256) state_k(const float* __restrict__ c_tm1,
                                               const float* __restrict__ n_tm1,
                                               const float* __restrict__ gn_g,
                                               const float* __restrict__ gn_b,
                                               float* __restrict__ out_c,
                                               float* __restrict__ out_n) {
    const int bh = blockIdx.x;
    const int b = bh >> 3, h = bh & 7;
    const int tid = threadIdx.x;
    __shared__ __align__(16) float qs[HD_], ks[HD_], vs[HD_], nums[HD_], tmp[HD_];
    __shared__ float s_den, s_mu, s_inv;

    const float fgv = g_s[OFF_FG + bh];
    const float igv = g_s[OFF_IG + bh];

    if (tid < HD_) {
        const int gi = b * HID_ + h * HD_ + tid;
        qs[tid] = g_s[OFF_Q + gi];
        ks[tid] = g_s[OFF_K + gi];
        vs[tid] = g_s[OFF_V + gi];
    }
    __syncthreads();

    // n_t and den = max(n_t . q, 1)
    if (tid < HD_) {
        float nn = fmaf(fgv, n_tm1[(size_t)bh * HD_ + tid], igv * ks[tid]);
        out_n[(size_t)bh * HD_ + tid] = nn;
        tmp[tid] = nn * qs[tid];
    }
    __syncthreads();
    if (tid < 32) {
        float ssum = tmp[tid] + tmp[tid + 32] + tmp[tid + 64] + tmp[tid + 96];
        ssum = warp_sum(ssum);
        if (tid == 0) s_den = fmaxf(ssum, 1.0f);
    }
    __syncthreads();

    // c_t = f*c_old + i*v k^T ; num[d] = c_t[d,:] . q   (warp per 16 rows, float4)
    const int w = tid >> 5, l = tid & 31;
    const size_t cbase = (size_t)bh * HD_ * HD_;
    const float4 k4 = reinterpret_cast<const float4*>(ks)[l];
    const float4 q4 = reinterpret_cast<const float4*>(qs)[l];
#pragma unroll 4
    for (int dd = 0; dd < 16; dd++) {
        const int d = w * 16 + dd;
        const float vd = vs[d] * igv;
        const size_t rb = cbase + (size_t)d * HD_;
        float4 c4 = reinterpret_cast<const float4*>(c_tm1 + rb)[l];
        float4 cn;
        cn.x = fmaf(fgv, c4.x, vd * k4.x);
        cn.y = fmaf(fgv, c4.y, vd * k4.y);
        cn.z = fmaf(fgv, c4.z, vd * k4.z);
        cn.w = fmaf(fgv, c4.w, vd * k4.w);
        reinterpret_cast<float4*>(out_c + rb)[l] = cn;
        float acc = cn.x*q4.x + cn.y*q4.y + cn.z*q4.z + cn.w*q4.w;
        acc = warp_sum(acc);
        if (l == 0) nums[d] = acc;
    }
    __syncthreads();

    // h = sigmoid(o) * num/den, then GroupNorm over the 128 dims of this head
    if (tid < HD_) {
        float hv = g_s[OFF_O + b * HID_ + h * HD_ + tid] * nums[tid] / s_den;
        tmp[tid] = hv;
    }
    __syncthreads();
    if (tid < 32) {
        float ssum = 0.f, ssq = 0.f;
#pragma unroll
        for (int pp = 0; pp < 4; pp++) {
            float x = tmp[tid + 32 * pp];
            ssum += x; ssq += x * x;
        }
        ssum = warp_sum(ssum); ssq = warp_sum(ssq);
        if (tid == 0) {
            float mu = ssum * (1.0f / HD_);
            float var = ssq * (1.0f / HD_) - mu * mu;
            s_mu = mu; s_inv = rsqrtf(var + EPS_);
        }
    }
    __syncthreads();
    if (tid < HD_) {
        const int gi = h * HD_ + tid;
        g_s[OFF_HN + b * HID_ + gi] = (tmp[tid] - s_mu) * s_inv * gn_g[gi] + gn_b[gi];
    }
}

// ---------------- launch ----------------
extern "C" void kernel_launch(void* const* d_in, const int* in_sizes, int n_in,
                              void* d_out, int out_size) {
    const float* seq    = (const float*)d_in[0];
    const float* c_tm1  = (const float*)d_in[1];
    const float* n_tm1  = (const float*)d_in[2];
    const float* m_tm1  = (const float*)d_in[3];
    const float* ln_g   = (const float*)d_in[4];
    const float* ln_b   = (const float*)d_in[5];
    const float* gn_g   = (const float*)d_in[6];
    const float* gn_b   = (const float*)d_in[7];
    const float* W_upl  = (const float*)d_in[8];
    const float* b_upl  = (const float*)d_in[9];
    const float* W_upr  = (const float*)d_in[10];
    const float* b_upr  = (const float*)d_in[11];
    const float* W_down = (const float*)d_in[12];
    const float* b_down = (const float*)d_in[13];
    const float* W_last = (const float*)d_in[14];
    const float* b_last = (const float*)d_in[15];
    const float* conv_w = (const float*)d_in[16];
    const float* conv_b = (const float*)d_in[17];
    const float* W_skip = (const float*)d_in[18];
    const float* W_i    = (const float*)d_in[19];
    const float* b_i    = (const float*)d_in[20];
    const float* W_f    = (const float*)d_in[21];
    const float* b_f    = (const float*)d_in[22];
    const float* W_o    = (const float*)d_in[23];
    const float* b_o    = (const float*)d_in[24];
    const float* W_q    = (const float*)d_in[25];
    const float* b_q    = (const float*)d_in[26];
    const float* W_k    = (const float*)d_in[27];
    const float* b_k    = (const float*)d_in[28];
    const float* W_v    = (const float*)d_in[29];
    const float* b_v    = (const float*)d_in[30];

    float* out       = (float*)d_out;
    float* out_final = out;                                    // [B,O]
    float* out_c     = out + (size_t)B_ * O_;                  // [B,H,HD,HD]
    float* out_n     = out_c + (size_t)B_ * H_ * HD_ * HD_;    // [B,H,HD]
    float* out_m     = out_n + (size_t)B_ * H_ * HD_;          // [B,H]

    void* sp = nullptr;
    cudaGetSymbolAddress(&sp, g_s);
    float* s = (float*)sp;

    const float kscale = 0.08838834764831843f;                 // 1/sqrt(128)

    // 1) input LayerNorm
    ln_k<<<B_, 256>>>(seq, ln_g, ln_b);
    // 2) up-projections (upl: 16x8=128 blocks; upr: 16x8=128 blocks)
    gemm3_k<128,4><<<dim3(P_/128, B_/32), 256>>>(s+OFF_XN, W_upl, b_upl, s+OFF_XT, D_, P_, nullptr, nullptr, 1.f, 0);
    gemm3_k<64,2><<<dim3(HID_/64, B_/32), 256>>>(s+OFF_XN, W_upr, b_upr, s+OFF_RS, D_, HID_, nullptr, nullptr, 1.f, 1);
    // 3) causal conv + silu
    conv_k<<<(B_*P_)/256, 256>>>(conv_w, conv_b);
    // 4) q,k,v,o in ONE batched launch: 8x8x4 = 256 blocks (2 blocks/SM)
    qkvo_k<<<dim3(HID_/128, B_/32, 4), 256>>>(W_q, b_q, W_k, b_k, W_v, b_v, W_o, b_o, kscale);
    // 5) i/f gates + stabilized exp
    gates_k<<<B_, 256>>>(W_i, b_i, W_f, b_f, m_tm1, out_m);
    // 6) state update + output gate + GroupNorm (single pass over c)
    state_k<<<B_*H_, 256>>>(c_tm1, n_tm1, gn_g, gn_b, out_c, out_n);
    // 7) skip-GEMM fused: (x_c@W_skip^T + hn) * silu(r)
    gemm3_k<64,2><<<dim3(HID_/64, B_/32), 256>>>(s+OFF_XC, W_skip, nullptr, s+OFF_O1, P_, HID_, s+OFF_HN, s+OFF_RS, 1.f, 4);
    // 8) down-GEMM fused residual: +x_n
    gemm3_k<64,2><<<dim3(D_/64, B_/32), 256>>>(s+OFF_O1, W_down, b_down, s+OFF_Y, HID_, D_, s+OFF_XN, nullptr, 1.f, 5);
    // 9) final projection -> d_out
    gemm3_k<64,2><<<dim3(O_/64, B_/32), 256>>>(s+OFF_Y, W_last, b_last, out_final, D_, O_, nullptr, nullptr, 1.f, 0);
}

// round 9
// speedup vs baseline: 2.1165x; 1.1957x over previous
#include <cuda_runtime.h>
#include <cuda_bf16.h>
#include <mma.h>
#include <math.h>
#include <stdint.h>

using namespace nvcuda;

// ---------------- problem constants ----------------
static constexpr int B_   = 256;
static constexpr int D_   = 1024;
static constexpr int H_   = 8;
static constexpr int HD_  = 128;
static constexpr int P_   = 2048;
static constexpr int HID_ = 1024;   // H*HD
static constexpr int O_   = 1024;
static constexpr float EPS_ = 1e-5f;

// ---------------- fp32 scratch layout ----------------
static constexpr int OFF_XN = 0;                  // [B,D]
static constexpr int OFF_XT = OFF_XN + B_*D_;     // [B,P]
static constexpr int OFF_XC = OFF_XT + B_*P_;     // [B,P]
static constexpr int OFF_RS = OFF_XC + B_*P_;     // [B,HID] silu(r)
static constexpr int OFF_Q  = OFF_RS + B_*HID_;   // [B,HID]
static constexpr int OFF_K  = OFF_Q  + B_*HID_;
static constexpr int OFF_V  = OFF_K  + B_*HID_;
static constexpr int OFF_O  = OFF_V  + B_*HID_;
static constexpr int OFF_IG = OFF_O  + B_*HID_;   // [B,H]
static constexpr int OFF_FG = OFF_IG + B_*H_;     // [B,H]
static constexpr int OFF_HN = OFF_FG + B_*H_;     // [B,HID]
static constexpr int SCRATCH_TOTAL = OFF_HN + B_*HID_;
__device__ __align__(16) float g_s[SCRATCH_TOTAL];

// ---------------- bf16 hi/lo activation arrays ----------------
static constexpr size_t AXN = 0;
static constexpr size_t AXT = AXN + (size_t)B_*D_;
static constexpr size_t AXC = AXT + (size_t)B_*P_;
static constexpr size_t AO1 = AXC + (size_t)B_*P_;
static constexpr size_t AY  = AO1 + (size_t)B_*HID_;
static constexpr size_t ACT_TOTAL = AY + (size_t)B_*D_;
__device__ __align__(16) __nv_bfloat16 g_ah[ACT_TOTAL];
__device__ __align__(16) __nv_bfloat16 g_al[ACT_TOTAL];

// weights (units of 2^20 elts): upl 2M | upr 1M | q 2M | k 2M | v 2M | o 2M | skip 2M | down 1M | last 1M
static constexpr size_t MEG = 1u << 20;
static constexpr size_t OFW_UPL  = 0;
static constexpr size_t OFW_UPR  = 2*MEG;
static constexpr size_t OFW_Q    = 3*MEG;
static constexpr size_t OFW_K    = 5*MEG;
static constexpr size_t OFW_V    = 7*MEG;
static constexpr size_t OFW_O    = 9*MEG;
static constexpr size_t OFW_SKIP = 11*MEG;
static constexpr size_t OFW_DOWN = 13*MEG;
static constexpr size_t OFW_LAST = 14*MEG;
static constexpr size_t W_TOTAL  = 15*MEG;
__device__ __align__(16) __nv_bfloat16 g_wh[W_TOTAL];
__device__ __align__(16) __nv_bfloat16 g_wl[W_TOTAL];

// ---------------- utils ----------------
__device__ __forceinline__ float warp_sum(float v) {
#pragma unroll
    for (int o = 16; o > 0; o >>= 1) v += __shfl_xor_sync(0xffffffffu, v, o);
    return v;
}
__device__ __forceinline__ void split_bf16(float x, __nv_bfloat16& h, __nv_bfloat16& l) {
    h = __float2bfloat16(x);
    l = __float2bfloat16(x - __bfloat162float(h));
}

// ============================================================================
// weight split: 9 fp32 weight matrices -> g_wh/g_wl (bf16 hi/lo)
// ============================================================================
__global__ void __launch_bounds__(256) wconv_k(
    const float* __restrict__ w_upl, const float* __restrict__ w_upr,
    const float* __restrict__ w_q,   const float* __restrict__ w_k,
    const float* __restrict__ w_v,   const float* __restrict__ w_o,
    const float* __restrict__ w_skip,const float* __restrict__ w_down,
    const float* __restrict__ w_last) {
    const size_t gidx = (size_t)blockIdx.x * 1024 + threadIdx.x * 4;
    const int seg = (int)(gidx >> 20);
    const float* src; size_t b0;
    if (seg < 2)       { src = w_upl;  b0 = OFW_UPL; }
    else if (seg < 3)  { src = w_upr;  b0 = OFW_UPR; }
    else if (seg < 5)  { src = w_q;    b0 = OFW_Q; }
    else if (seg < 7)  { src = w_k;    b0 = OFW_K; }
    else if (seg < 9)  { src = w_v;    b0 = OFW_V; }
    else if (seg < 11) { src = w_o;    b0 = OFW_O; }
    else if (seg < 13) { src = w_skip; b0 = OFW_SKIP; }
    else if (seg < 14) { src = w_down; b0 = OFW_DOWN; }
    else               { src = w_last; b0 = OFW_LAST; }
    float4 x = *reinterpret_cast<const float4*>(src + (gidx - b0));
    __nv_bfloat16 h0,h1,h2,h3,l0,l1,l2,l3;
    split_bf16(x.x,h0,l0); split_bf16(x.y,h1,l1); split_bf16(x.z,h2,l2); split_bf16(x.w,h3,l3);
    uint2 hp, lp;
    hp.x = (uint32_t)__bfloat16_as_ushort(h0) | ((uint32_t)__bfloat16_as_ushort(h1) << 16);
    hp.y = (uint32_t)__bfloat16_as_ushort(h2) | ((uint32_t)__bfloat16_as_ushort(h3) << 16);
    lp.x = (uint32_t)__bfloat16_as_ushort(l0) | ((uint32_t)__bfloat16_as_ushort(l1) << 16);
    lp.y = (uint32_t)__bfloat16_as_ushort(l2) | ((uint32_t)__bfloat16_as_ushort(l3) << 16);
    *reinterpret_cast<uint2*>(g_wh + gidx) = hp;
    *reinterpret_cast<uint2*>(g_wl + gidx) = lp;
}

// ============================================================================
// wmma bf16-split GEMM core.  C[m,n] = (sum_k A[m,k]*W[n,k] + bias[n])*scale, EPI
//  A,W given as bf16 hi/lo, K-major. D = hi*hi + hi*lo + lo*hi (fp32 accum).
//  Tile: BM=64, BN=64, K-stage=32, 256 threads (8 warps: 4m x 2n, warp 16x32).
//  epi: 0 none, 1 silu, 2 sigmoid, 4 (v+e1)*e2, 5 v+e1
// ============================================================================
static constexpr int LDT = 40;                     // bf16 leading dim (80B rows, conflict-free)
static constexpr int STG_A  = 64 * LDT;            // 2560 bf16 per array
static constexpr int STG_AH = 0;
static constexpr int STG_AL = STG_A;
static constexpr int STG_WH = 2 * STG_A;
static constexpr int STG_WL = 3 * STG_A;
static constexpr int STG_TOTAL = 4 * STG_A;        // 10240 bf16 = 20480 B per stage

__device__ __forceinline__ void wm_gemm_core(
        const __nv_bfloat16* __restrict__ Ahi, const __nv_bfloat16* __restrict__ Alo,
        const __nv_bfloat16* __restrict__ Whi, const __nv_bfloat16* __restrict__ Wlo,
        const float* __restrict__ bias,
        float* __restrict__ Cf32,
        __nv_bfloat16* __restrict__ Chi, __nv_bfloat16* __restrict__ Clo,
        int Kd, int N, int m0, int n0,
        const float* __restrict__ e1, const float* __restrict__ e2,
        float scale, int epi) {
    __shared__ __align__(16) __nv_bfloat16 stg[2][STG_TOTAL];

    const int tid = threadIdx.x, wid = tid >> 5;
    const int wm = wid >> 1, wn = wid & 1;          // warp tile: rows wm*16, cols wn*32

    // per-thread staging: row = tid>>2 (0..63), q = tid&3 (16B chunk within 32-elt row)
    const int row = tid >> 2, q = tid & 3;
    const size_t rK = (size_t)Kd;
    const __nv_bfloat16* pAh = Ahi + (size_t)(m0 + row) * rK + q * 8;
    const __nv_bfloat16* pAl = Alo + (size_t)(m0 + row) * rK + q * 8;
    const __nv_bfloat16* pWh = Whi + (size_t)(n0 + row) * rK + q * 8;
    const __nv_bfloat16* pWl = Wlo + (size_t)(n0 + row) * rK + q * 8;
    const int sdst = row * LDT + q * 8;

    wmma::fragment<wmma::accumulator, 16, 16, 16, float> acc[2];
    wmma::fill_fragment(acc[0], 0.f);
    wmma::fill_fragment(acc[1], 0.f);

    const int T = Kd >> 5;
    // prologue: stage 0
    {
        *reinterpret_cast<uint4*>(&stg[0][STG_AH + sdst]) = *reinterpret_cast<const uint4*>(pAh);
        *reinterpret_cast<uint4*>(&stg[0][STG_AL + sdst]) = *reinterpret_cast<const uint4*>(pAl);
        *reinterpret_cast<uint4*>(&stg[0][STG_WH + sdst]) = *reinterpret_cast<const uint4*>(pWh);
        *reinterpret_cast<uint4*>(&stg[0][STG_WL + sdst]) = *reinterpret_cast<const uint4*>(pWl);
    }
    __syncthreads();

    int buf = 0;
    for (int t = 0; t < T; t++) {
        uint4 ra, rb, rc, rd;
        const bool more = (t + 1 < T);
        if (more) {
            const int off = (t + 1) * 32;
            ra = *reinterpret_cast<const uint4*>(pAh + off);
            rb = *reinterpret_cast<const uint4*>(pAl + off);
            rc = *reinterpret_cast<const uint4*>(pWh + off);
            rd = *reinterpret_cast<const uint4*>(pWl + off);
        }
        const __nv_bfloat16* sb = stg[buf];
#pragma unroll
        for (int kk = 0; kk < 32; kk += 16) {
            wmma::fragment<wmma::matrix_a, 16, 16, 16, __nv_bfloat16, wmma::row_major> a_h, a_l;
            wmma::fragment<wmma::matrix_b, 16, 16, 16, __nv_bfloat16, wmma::col_major> b_h[2], b_l[2];
            wmma::load_matrix_sync(a_h, sb + STG_AH + (wm * 16) * LDT + kk, LDT);
            wmma::load_matrix_sync(a_l, sb + STG_AL + (wm * 16) * LDT + kk, LDT);
#pragma unroll
            for (int nj = 0; nj < 2; nj++) {
                wmma::load_matrix_sync(b_h[nj], sb + STG_WH + (wn * 32 + nj * 16) * LDT + kk, LDT);
                wmma::load_matrix_sync(b_l[nj], sb + STG_WL + (wn * 32 + nj * 16) * LDT + kk, LDT);
            }
#pragma unroll
            for (int nj = 0; nj < 2; nj++) {
                wmma::mma_sync(acc[nj], a_h, b_h[nj], acc[nj]);
                wmma::mma_sync(acc[nj], a_h, b_l[nj], acc[nj]);
                wmma::mma_sync(acc[nj], a_l, b_h[nj], acc[nj]);
            }
        }
        if (more) {
            const int nb = buf ^ 1;
            *reinterpret_cast<uint4*>(&stg[nb][STG_AH + sdst]) = ra;
            *reinterpret_cast<uint4*>(&stg[nb][STG_AL + sdst]) = rb;
            *reinterpret_cast<uint4*>(&stg[nb][STG_WH + sdst]) = rc;
            *reinterpret_cast<uint4*>(&stg[nb][STG_WL + sdst]) = rd;
            __syncthreads();
            buf = nb;
        }
    }

    // epilogue: acc -> smem fp32 (reuse staging buffer 0: 64*72*4 = 18432 B <= 20480 B)
    __syncthreads();
    float* eps = reinterpret_cast<float*>(&stg[0][0]);
#pragma unroll
    for (int nj = 0; nj < 2; nj++)
        wmma::store_matrix_sync(eps + (wm * 16) * 72 + wn * 32 + nj * 16, acc[nj], 72, wmma::mem_row_major);
    __syncthreads();

    const int c = tid & 63;
    const int n = n0 + c;
    const float bn = bias ? bias[n] : 0.f;
#pragma unroll 4
    for (int i = 0; i < 16; i++) {
        const int ml = (tid >> 6) + i * 4;
        const int m = m0 + ml;
        float v = (eps[ml * 72 + c] + bn) * scale;
        const size_t idx = (size_t)m * N + n;
        if (epi == 1) v = v / (1.f + expf(-v));
        else if (epi == 2) v = 1.f / (1.f + expf(-v));
        else if (epi == 4) v = (v + e1[idx]) * e2[idx];
        else if (epi == 5) v = v + e1[idx];
        if (Cf32) Cf32[idx] = v;
        if (Chi) {
            __nv_bfloat16 h, l; split_bf16(v, h, l);
            Chi[idx] = h; Clo[idx] = l;
        }
    }
}

// generic single-GEMM wrapper: grid (N/64, 256/64)
__global__ void __launch_bounds__(256) wm_gemm_k(
    const __nv_bfloat16* Ahi, const __nv_bfloat16* Alo,
    const __nv_bfloat16* Whi, const __nv_bfloat16* Wlo,
    const float* bias, float* Cf32, __nv_bfloat16* Chi, __nv_bfloat16* Clo,
    int Kd, int N, const float* e1, const float* e2, float scale, int epi) {
    wm_gemm_core(Ahi, Alo, Whi, Wlo, bias, Cf32, Chi, Clo, Kd, N,
                 blockIdx.y * 64, blockIdx.x * 64, e1, e2, scale, epi);
}

// batched q/k/v/o: grid (16, 4, 4)
__global__ void __launch_bounds__(256) wm_qkvo_k(
    const float* b_q, const float* b_k, const float* b_v, const float* b_o, float kscale) {
    const int z = blockIdx.z;
    const size_t aoff = (z < 2) ? AXC : AXT;
    const size_t woff = OFW_Q + (size_t)z * (2 * MEG);
    const float* bias = (z == 0) ? b_q : (z == 1) ? b_k : (z == 2) ? b_v : b_o;
    float* C = g_s + OFF_Q + (size_t)z * B_ * HID_;
    wm_gemm_core(g_ah + aoff, g_al + aoff, g_wh + woff, g_wl + woff,
                 bias, C, nullptr, nullptr, P_, HID_,
                 blockIdx.y * 64, blockIdx.x * 64,
                 nullptr, nullptr, (z == 1) ? kscale : 1.f, (z == 3) ? 2 : 0);
}

// ---------------- LayerNorm: seq -> xn fp32 + bf16 hi/lo ----------------
__global__ void __launch_bounds__(256) ln_k(const float* __restrict__ seq,
                                            const float* __restrict__ g,
                                            const float* __restrict__ bt) {
    const int row = blockIdx.x, tid = threadIdx.x;
    const int wid = tid >> 5, lane = tid & 31;
    float4 x = reinterpret_cast<const float4*>(seq + row * D_)[tid];
    float s  = x.x + x.y + x.z + x.w;
    float q2 = x.x*x.x + x.y*x.y + x.z*x.z + x.w*x.w;
    s = warp_sum(s); q2 = warp_sum(q2);
    __shared__ float ssum[8], ssq[8];
    __shared__ float s_mu, s_inv;
    if (lane == 0) { ssum[wid] = s; ssq[wid] = q2; }
    __syncthreads();
    if (tid == 0) {
        float S = 0.f, Q = 0.f;
#pragma unroll
        for (int i = 0; i < 8; i++) { S += ssum[i]; Q += ssq[i]; }
        float mu = S * (1.0f / D_);
        float var = Q * (1.0f / D_) - mu * mu;
        s_mu = mu; s_inv = rsqrtf(var + EPS_);
    }
    __syncthreads();
    float4 gg = reinterpret_cast<const float4*>(g)[tid];
    float4 bb = reinterpret_cast<const float4*>(bt)[tid];
    float4 o;
    o.x = (x.x - s_mu) * s_inv * gg.x + bb.x;
    o.y = (x.y - s_mu) * s_inv * gg.y + bb.y;
    o.z = (x.z - s_mu) * s_inv * gg.z + bb.z;
    o.w = (x.w - s_mu) * s_inv * gg.w + bb.w;
    reinterpret_cast<float4*>(g_s + OFF_XN + row * D_)[tid] = o;
    __nv_bfloat16 h0,h1,h2,h3,l0,l1,l2,l3;
    split_bf16(o.x,h0,l0); split_bf16(o.y,h1,l1); split_bf16(o.z,h2,l2); split_bf16(o.w,h3,l3);
    uint2 hp, lp;
    hp.x = (uint32_t)__bfloat16_as_ushort(h0) | ((uint32_t)__bfloat16_as_ushort(h1) << 16);
    hp.y = (uint32_t)__bfloat16_as_ushort(h2) | ((uint32_t)__bfloat16_as_ushort(h3) << 16);
    lp.x = (uint32_t)__bfloat16_as_ushort(l0) | ((uint32_t)__bfloat16_as_ushort(l1) << 16);
    lp.y = (uint32_t)__bfloat16_as_ushort(l2) | ((uint32_t)__bfloat16_as_ushort(l3) << 16);
    *reinterpret_cast<uint2*>(g_ah + AXN + (size_t)row * D_ + tid * 4) = hp;
    *reinterpret_cast<uint2*>(g_al + AXN + (size_t)row * D_ + tid * 4) = lp;
}

// ---------------- causal conv (K=4) + silu: xt -> xc fp32 + bf16 hi/lo ----------------
__global__ void __launch_bounds__(256) conv_k(const float* __restrict__ cw,
                                              const float* __restrict__ cb) {
    const int idx = blockIdx.x * 256 + threadIdx.x;
    const int b = idx >> 11, p = idx & (P_ - 1);
    const float* xt = g_s + OFF_XT + (size_t)b * P_;
    float v = cb[0];
    if (p >= 3) v = fmaf(cw[0], xt[p - 3], v);
    if (p >= 2) v = fmaf(cw[1], xt[p - 2], v);
    if (p >= 1) v = fmaf(cw[2], xt[p - 1], v);
    v = fmaf(cw[3], xt[p], v);
    v = v / (1.f + expf(-v));
    g_s[OFF_XC + idx] = v;
    __nv_bfloat16 h, l; split_bf16(v, h, l);
    g_ah[AXC + idx] = h;
    g_al[AXC + idx] = l;
}

// ---------------- gates ----------------
__global__ void __launch_bounds__(256) gates_k(const float* __restrict__ W_i,
                                               const float* __restrict__ b_i,
                                               const float* __restrict__ W_f,
                                               const float* __restrict__ b_f,
                                               const float* __restrict__ m_tm1,
                                               float* __restrict__ out_m) {
    const int b = blockIdx.x;
    const int h = threadIdx.x >> 5, l = threadIdx.x & 31;
    const float4* xc = reinterpret_cast<const float4*>(g_s + OFF_XC + (size_t)b * P_);
    const float4* wi = reinterpret_cast<const float4*>(W_i + (size_t)h * P_);
    const float4* wf = reinterpret_cast<const float4*>(W_f + (size_t)h * P_);
    float ai = 0.f, af = 0.f;
    for (int j = l; j < P_ / 4; j += 32) {
        float4 x = xc[j], vi = wi[j], vf = wf[j];
        ai = fmaf(x.x, vi.x, fmaf(x.y, vi.y, fmaf(x.z, vi.z, fmaf(x.w, vi.w, ai))));
        af = fmaf(x.x, vf.x, fmaf(x.y, vf.y, fmaf(x.z, vf.z, fmaf(x.w, vf.w, af))));
    }
    ai = warp_sum(ai); af = warp_sum(af);
    if (l == 0) {
        float it = ai + b_i[h];
        float ft = af + b_f[h];
        float mp = m_tm1[b * H_ + h];
        float mt = fmaxf(ft + mp, it);
        out_m[b * H_ + h] = mt;
        g_s[OFF_IG + b * H_ + h] = expf(it - mt);
        g_s[OFF_FG + b * H_ + h] = expf(ft - mt + mp);
    }
}

// ---------------- state update (single pass over c) ----------------
__global__ void __launch_bounds__(256) state_k(const float* __restrict__ c_tm1,
                                               const float* __restrict__ n_tm1,
                                               const float* __restrict__ gn_g,
                                               const float* __restrict__ gn_b,
                                               float* __restrict__ out_c,
                                               float* __restrict__ out_n) {
    const int bh = blockIdx.x;
    const int b = bh >> 3, h = bh & 7;
    const int tid = threadIdx.x;
    __shared__ __align__(16) float qs[HD_], ks[HD_], vs[HD_], nums[HD_], tmp[HD_];
    __shared__ float s_den, s_mu, s_inv;

    const float fgv = g_s[OFF_FG + bh];
    const float igv = g_s[OFF_IG + bh];

    if (tid < HD_) {
        const int gi = b * HID_ + h * HD_ + tid;
        qs[tid] = g_s[OFF_Q + gi];
        ks[tid] = g_s[OFF_K + gi];
        vs[tid] = g_s[OFF_V + gi];
    }
    __syncthreads();

    if (tid < HD_) {
        float nn = fmaf(fgv, n_tm1[(size_t)bh * HD_ + tid], igv * ks[tid]);
        out_n[(size_t)bh * HD_ + tid] = nn;
        tmp[tid] = nn * qs[tid];
    }
    __syncthreads();
    if (tid < 32) {
        float ssum = tmp[tid] + tmp[tid + 32] + tmp[tid + 64] + tmp[tid + 96];
        ssum = warp_sum(ssum);
        if (tid == 0) s_den = fmaxf(ssum, 1.0f);
    }
    __syncthreads();

    const int w = tid >> 5, l = tid & 31;
    const size_t cbase = (size_t)bh * HD_ * HD_;
    const float4 k4 = reinterpret_cast<const float4*>(ks)[l];
    const float4 q4 = reinterpret_cast<const float4*>(qs)[l];
#pragma unroll 4
    for (int dd = 0; dd < 16; dd++) {
        const int d = w * 16 + dd;
        const float vd = vs[d] * igv;
        const size_t rb = cbase + (size_t)d * HD_;
        float4 c4 = reinterpret_cast<const float4*>(c_tm1 + rb)[l];
        float4 cn;
        cn.x = fmaf(fgv, c4.x, vd * k4.x);
        cn.y = fmaf(fgv, c4.y, vd * k4.y);
        cn.z = fmaf(fgv, c4.z, vd * k4.z);
        cn.w = fmaf(fgv, c4.w, vd * k4.w);
        reinterpret_cast<float4*>(out_c + rb)[l] = cn;
        float acc = cn.x*q4.x + cn.y*q4.y + cn.z*q4.z + cn.w*q4.w;
        acc = warp_sum(acc);
        if (l == 0) nums[d] = acc;
    }
    __syncthreads();

    if (tid < HD_) {
        float hv = g_s[OFF_O + b * HID_ + h * HD_ + tid] * nums[tid] / s_den;
        tmp[tid] = hv;
    }
    __syncthreads();
    if (tid < 32) {
        float ssum = 0.f, ssq = 0.f;
#pragma unroll
        for (int pp = 0; pp < 4; pp++) {
            float x = tmp[tid + 32 * pp];
            ssum += x; ssq += x * x;
        }
        ssum = warp_sum(ssum); ssq = warp_sum(ssq);
        if (tid == 0) {
            float mu = ssum * (1.0f / HD_);
            float var = ssq * (1.0f / HD_) - mu * mu;
            s_mu = mu; s_inv = rsqrtf(var + EPS_);
        }
    }
    __syncthreads();
    if (tid < HD_) {
        const int gi = h * HD_ + tid;
        g_s[OFF_HN + b * HID_ + gi] = (tmp[tid] - s_mu) * s_inv * gn_g[gi] + gn_b[gi];
    }
}

// ---------------- launch ----------------
extern "C" void kernel_launch(void* const* d_in, const int* in_sizes, int n_in,
                              void* d_out, int out_size) {
    const float* seq    = (const float*)d_in[0];
    const float* c_tm1  = (const float*)d_in[1];
    const float* n_tm1  = (const float*)d_in[2];
    const float* m_tm1  = (const float*)d_in[3];
    const float* ln_g   = (const float*)d_in[4];
    const float* ln_b   = (const float*)d_in[5];
    const float* gn_g   = (const float*)d_in[6];
    const float* gn_b   = (const float*)d_in[7];
    const float* W_upl  = (const float*)d_in[8];
    const float* b_upl  = (const float*)d_in[9];
    const float* W_upr  = (const float*)d_in[10];
    const float* b_upr  = (const float*)d_in[11];
    const float* W_down = (const float*)d_in[12];
    const float* b_down = (const float*)d_in[13];
    const float* W_last = (const float*)d_in[14];
    const float* b_last = (const float*)d_in[15];
    const float* conv_w = (const float*)d_in[16];
    const float* conv_b = (const float*)d_in[17];
    const float* W_skip = (const float*)d_in[18];
    const float* W_i    = (const float*)d_in[19];
    const float* b_i    = (const float*)d_in[20];
    const float* W_f    = (const float*)d_in[21];
    const float* b_f    = (const float*)d_in[22];
    const float* W_o    = (const float*)d_in[23];
    const float* b_o    = (const float*)d_in[24];
    const float* W_q    = (const float*)d_in[25];
    const float* b_q    = (const float*)d_in[26];
    const float* W_k    = (const float*)d_in[27];
    const float* b_k    = (const float*)d_in[28];
    const float* W_v    = (const float*)d_in[29];
    const float* b_v    = (const float*)d_in[30];

    float* out       = (float*)d_out;
    float* out_final = out;
    float* out_c     = out + (size_t)B_ * O_;
    float* out_n     = out_c + (size_t)B_ * H_ * HD_ * HD_;
    float* out_m     = out_n + (size_t)B_ * H_ * HD_;

    void* sp = nullptr;  cudaGetSymbolAddress(&sp, g_s);
    float* s = (float*)sp;
    void* ahp = nullptr; cudaGetSymbolAddress(&ahp, g_ah);
    void* alp = nullptr; cudaGetSymbolAddress(&alp, g_al);
    void* whp = nullptr; cudaGetSymbolAddress(&whp, g_wh);
    void* wlp = nullptr; cudaGetSymbolAddress(&wlp, g_wl);
    __nv_bfloat16* ah = (__nv_bfloat16*)ahp;
    __nv_bfloat16* al = (__nv_bfloat16*)alp;
    __nv_bfloat16* wh = (__nv_bfloat16*)whp;
    __nv_bfloat16* wl = (__nv_bfloat16*)wlp;

    const float kscale = 0.08838834764831843f;  // 1/sqrt(128)

    // 0) weight bf16 split
    wconv_k<<<(int)(W_TOTAL / 1024), 256>>>(W_upl, W_upr, W_q, W_k, W_v, W_o, W_skip, W_down, W_last);
    // 1) input LayerNorm (fp32 + bf16 split)
    ln_k<<<B_, 256>>>(seq, ln_g, ln_b);
    // 2) up-projections
    wm_gemm_k<<<dim3(P_/64, B_/64), 256>>>(
        ah + AXN, al + AXN, wh + OFW_UPL, wl + OFW_UPL, b_upl,
        s + OFF_XT, ah + AXT, al + AXT, D_, P_, nullptr, nullptr, 1.f, 0);
    wm_gemm_k<<<dim3(HID_/64, B_/64), 256>>>(
        ah + AXN, al + AXN, wh + OFW_UPR, wl + OFW_UPR, b_upr,
        s + OFF_RS, nullptr, nullptr, D_, HID_, nullptr, nullptr, 1.f, 1);
    // 3) causal conv + silu (fp32 + bf16 split)
    conv_k<<<(B_*P_)/256, 256>>>(conv_w, conv_b);
    // 4) q,k,v,o batched (256 CTAs)
    wm_qkvo_k<<<dim3(HID_/64, B_/64, 4), 256>>>(b_q, b_k, b_v, b_o, kscale);
    // 5) gates
    gates_k<<<B_, 256>>>(W_i, b_i, W_f, b_f, m_tm1, out_m);
    // 6) state update + GroupNorm
    state_k<<<B_*H_, 256>>>(c_tm1, n_tm1, gn_g, gn_b, out_c, out_n);
    // 7) skip: (xc@W_skip^T + hn) * rs  -> o1 (bf16 split only)
    wm_gemm_k<<<dim3(HID_/64, B_/64), 256>>>(
        ah + AXC, al + AXC, wh + OFW_SKIP, wl + OFW_SKIP, nullptr,
        nullptr, ah + AO1, al + AO1, P_, HID_, s + OFF_HN, s + OFF_RS, 1.f, 4);
    // 8) down: o1@W_down^T + b + xn -> y (bf16 split only)
    wm_gemm_k<<<dim3(D_/64, B_/64), 256>>>(
        ah + AO1, al + AO1, wh + OFW_DOWN, wl + OFW_DOWN, b_down,
        nullptr, ah + AY, al + AY, HID_, D_, s + OFF_XN, nullptr, 1.f, 5);
    // 9) last: y@W_last^T + b -> out
    wm_gemm_k<<<dim3(O_/64, B_/64), 256>>>(
        ah + AY, al + AY, wh + OFW_LAST, wl + OFW_LAST, b_last,
        out_final, nullptr, nullptr, D_, O_, nullptr, nullptr, 1.f, 0);
}